// round 12
// baseline (speedup 1.0000x reference)
#include <cuda_runtime.h>
#include <cuda_fp16.h>
#include <math.h>
#include <stdint.h>

#define N_NODES 50000
#define NEDGE   600000
#define IN_DIM  320

#define NT1   782          // node tiles of 64 rows
#define NT2   9375         // edge tiles of 64 edges (9375*64 == NEDGE)
#define PAIRS 148          // persistent k2 tile-pair stride (grid = 296)
#define GRID4 1563         // ceil(N_NODES/32)

// ---------------- scratch ----------------
__device__ __half g_h[(size_t)N_NODES * 512];    // 51.2 MB -> keep L2-resident
__device__ __half g_g[(size_t)NEDGE * 256];      // 307.2 MB, streamed (.cs)
__device__ float  g_s[(size_t)N_NODES * 128];
__device__ float  g_part1[2 * PAIRS * 256];      // [pair*2+half][sum128|sq128]
__device__ float  g_part2[GRID4 * 256];
__device__ float  g_bn1_scale[256], g_bn1_shift[256];
__device__ float  g_bn2_scale[128], g_bn2_shift[128];
__device__ int    g_idx64;

// ---------------- helpers ----------------
__device__ __forceinline__ uint32_t smem_u32(const void* p) {
    uint32_t a;
    asm("{ .reg .u64 t; cvta.to.shared.u64 t, %1; cvt.u32.u64 %0, t; }" : "=r"(a) : "l"(p));
    return a;
}
#define LDSM_X4(r, addr) \
    asm volatile("ldmatrix.sync.aligned.m8n8.x4.shared.b16 {%0,%1,%2,%3}, [%4];" \
        : "=r"((r)[0]), "=r"((r)[1]), "=r"((r)[2]), "=r"((r)[3]) : "r"(addr))

__device__ __forceinline__ void mma_f16(float* d, const uint32_t* a, const uint32_t* b) {
    asm volatile(
        "mma.sync.aligned.m16n8k16.row.col.f32.f16.f16.f32 "
        "{%0,%1,%2,%3}, {%4,%5,%6,%7}, {%8,%9}, {%0,%1,%2,%3};\n"
        : "+f"(d[0]), "+f"(d[1]), "+f"(d[2]), "+f"(d[3])
        : "r"(a[0]), "r"(a[1]), "r"(a[2]), "r"(a[3]), "r"(b[0]), "r"(b[1]));
}
// streaming (evict-first) global access for the write-once/read-once g tensor
__device__ __forceinline__ void stg_cs_h2(__half2* p, __half2 v) {
    uint32_t u = *(uint32_t*)&v;
    asm volatile("st.global.cs.u32 [%0], %1;" :: "l"(p), "r"(u) : "memory");
}
__device__ __forceinline__ float2 ldg_cs_h2f(const __half2* p) {
    uint32_t u;
    asm volatile("ld.global.cs.u32 %0, [%1];" : "=r"(u) : "l"(p));
    __half2 h = *(__half2*)&u;
    return __half22float2(h);
}
__device__ __forceinline__ float sigmoidf_(float x) {
    return __fdividef(1.0f, 1.0f + __expf(-x));
}
__device__ __forceinline__ float softplusf_(float x) {
    float t = __expf(-fabsf(x));
    return fmaxf(x, 0.0f) + __logf(1.0f + t);
}

// ================= k1: node GEMM (fp16 mma m16n8k16 + LDSM), h fp16 =================
// tile 64 nodes x 128 out, K=128; grid (NT1, 2 input-halves, 2 N-halves)
// block (0,0,0) also performs the edge_index dtype detection (k2 runs after k1).
#define K1_W_STRIDE 136                     // halves per W row (128 + 8 pad)
#define K1_A_STRIDE 136
#define K1_W_BYTES (128 * K1_W_STRIDE * 2)  // 34816
#define K1_A_BYTES (64 * K1_A_STRIDE * 2)   // 17408
#define K1_SMEM (K1_W_BYTES + K1_A_BYTES)   // 52224

__global__ void __launch_bounds__(256, 2)
k1_gemm(const float* __restrict__ x, const float* __restrict__ W,
        const void* __restrict__ ei) {
    extern __shared__ char smc[];
    __half* wt_h = (__half*)smc;                       // [n 0..127][k 0..127]
    __half* as_h = (__half*)(smc + K1_W_BYTES);        // [row 0..63][k 0..127]

    const int tid = threadIdx.x, lane = tid & 31, w = tid >> 5;
    const int g = lane >> 2, tg = lane & 3;
    const int wr = (w >> 2) * 32, wc = (w & 3) * 32;
    const int i0 = blockIdx.x * 64;
    const int woff = blockIdx.y * 128;
    const int zn = blockIdx.z * 128;

    // fused dtype detect (one block, one thread)
    if (blockIdx.x == 0 && blockIdx.y == 0 && blockIdx.z == 0 && tid == 0) {
        const long long* p = (const long long*)ei;
        int ok = 1;
        #pragma unroll
        for (int q = 0; q < 8; ++q) {
            long long v = p[NEDGE / 2 + q];
            if (v < 0 || v >= N_NODES) ok = 0;
        }
        g_idx64 = ok;
    }

    for (int idx = tid; idx < 128 * 128; idx += 256) {
        int n = idx >> 7, k = idx & 127;
        wt_h[n * K1_W_STRIDE + k] = __float2half_rn(W[(zn + n) * IN_DIM + woff + k]);
    }
    #pragma unroll
    for (int q = 0; q < 8; ++q) {
        int i4 = tid + q * 256;
        int er = i4 >> 5, kk = (i4 & 31) * 4;
        int i = i0 + er;
        float4 v = (i < N_NODES) ? ((const float4*)x)[(size_t)i * 32 + (kk >> 2)]
                                 : make_float4(0.f, 0.f, 0.f, 0.f);
        __half2* dst = (__half2*)(as_h + er * K1_A_STRIDE + kk);
        dst[0] = __floats2half2_rn(v.x, v.y);
        dst[1] = __floats2half2_rn(v.z, v.w);
    }
    __syncthreads();

    const uint32_t sA = smem_u32(as_h), sW = smem_u32(wt_h);
    const uint32_t aAddr0 = sA + (wr + (lane & 15)) * (K1_A_STRIDE * 2) + (lane >> 4) * 16;
    const uint32_t aAddr1 = aAddr0 + 16 * K1_A_STRIDE * 2;
    const uint32_t bAddr0 = sW + (wc + (lane & 7) + ((lane >> 4) & 1) * 8) * (K1_W_STRIDE * 2)
                               + ((lane >> 3) & 1) * 16;
    const uint32_t bAddr1 = bAddr0 + 16 * K1_W_STRIDE * 2;

    float acc[2][4][4];
    #pragma unroll
    for (int mt = 0; mt < 2; ++mt)
        #pragma unroll
        for (int nt = 0; nt < 4; ++nt)
            #pragma unroll
            for (int q = 0; q < 4; ++q) acc[mt][nt][q] = 0.0f;

    #pragma unroll
    for (int ks = 0; ks < 8; ++ks) {
        const uint32_t off = ks * 32;          // 16 halves
        uint32_t A0[4], A1[4], B0[4], B1[4];
        LDSM_X4(A0, aAddr0 + off);
        LDSM_X4(A1, aAddr1 + off);
        LDSM_X4(B0, bAddr0 + off);
        LDSM_X4(B1, bAddr1 + off);
        mma_f16(acc[0][0], A0, B0);     mma_f16(acc[1][0], A1, B0);
        mma_f16(acc[0][1], A0, B0 + 2); mma_f16(acc[1][1], A1, B0 + 2);
        mma_f16(acc[0][2], A0, B1);     mma_f16(acc[1][2], A1, B1);
        mma_f16(acc[0][3], A0, B1 + 2); mma_f16(acc[1][3], A1, B1 + 2);
    }

    const int hoff = blockIdx.y * 256 + zn;
    #pragma unroll
    for (int mt = 0; mt < 2; ++mt)
        #pragma unroll
        for (int rr = 0; rr < 2; ++rr) {
            int i = i0 + wr + mt * 16 + rr * 8 + g;
            if (i < N_NODES) {
                __half* ho = g_h + (size_t)i * 512 + hoff;
                #pragma unroll
                for (int nt = 0; nt < 4; ++nt) {
                    int c = wc + nt * 8 + 2 * tg;
                    *(__half2*)(ho + c) =
                        __floats2half2_rn(acc[mt][nt][rr * 2], acc[mt][nt][rr * 2 + 1]);
                }
            }
        }
}

// ================= k2: edge GEMM half-tile (fp16 mma) + gather + fused BN1 stats =================
#define K2_W_STRIDE 72
#define K2_A_STRIDE 72
#define K2_W_BYTES (128 * K2_W_STRIDE * 2)  // 18432
#define K2_A_BYTES (64 * K2_A_STRIDE * 2)   //  9216
#define K2_BS_OFF  (K2_W_BYTES + K2_A_BYTES)
#define K2_NBS_OFF (K2_BS_OFF + 128 * 4)
#define K2_SRED_OFF (K2_NBS_OFF + 64 * 4)
#define K2_SMEM (K2_SRED_OFF + 8 * 64 * 4)  // 30464

__global__ void __launch_bounds__(256, 2)
k2_edge(const float* __restrict__ ea, const void* __restrict__ ei,
        const float* __restrict__ W, const float* __restrict__ b) {
    extern __shared__ char smc[];
    __half* wt_h = (__half*)smc;                   // [n 0..127][k 0..63]
    __half* as_h = (__half*)(smc + K2_W_BYTES);    // [edge][k]
    float* bs = (float*)(smc + K2_BS_OFF);
    int*  nbs = (int*)(smc + K2_NBS_OFF);
    float* sred = (float*)(smc + K2_SRED_OFF);

    const int tid = threadIdx.x, lane = tid & 31, w = tid >> 5;
    const int g = lane >> 2, tg = lane & 3;
    const int wr = (w >> 2) * 32, wc = (w & 3) * 32;
    const int pair = blockIdx.x >> 1, half = blockIdx.x & 1;
    const int chb = half * 128;

    for (int idx = tid; idx < 128 * 64; idx += 256) {
        int n = idx >> 6, k = idx & 63;
        wt_h[n * K2_W_STRIDE + k] = __float2half_rn(W[(chb + n) * IN_DIM + 256 + k]);
    }
    if (tid < 128) bs[tid] = b[chb + tid];
    const int use64 = g_idx64;

    const uint32_t sA = smem_u32(as_h), sW = smem_u32(wt_h);
    const uint32_t aAddr0 = sA + (wr + (lane & 15)) * (K2_A_STRIDE * 2) + (lane >> 4) * 16;
    const uint32_t aAddr1 = aAddr0 + 16 * K2_A_STRIDE * 2;
    const uint32_t bAddr0 = sW + (wc + (lane & 7) + ((lane >> 4) & 1) * 8) * (K2_W_STRIDE * 2)
                               + ((lane >> 3) & 1) * 16;
    const uint32_t bAddr1 = bAddr0 + 16 * K2_W_STRIDE * 2;

    float ssum[8], ssq[8];
    #pragma unroll
    for (int q = 0; q < 8; ++q) { ssum[q] = 0.0f; ssq[q] = 0.0f; }

    // ---- prefetch first tile (converted to half2 in regs) ----
    __half2 pvh[8];
    int pnb = 0;
    int tile = pair;
    {
        const float4* src4 = (const float4*)(ea + (size_t)tile * 64 * 64);
        #pragma unroll
        for (int q = 0; q < 4; ++q) {
            float4 v = src4[tid + q * 256];
            pvh[2 * q]     = __floats2half2_rn(v.x, v.y);
            pvh[2 * q + 1] = __floats2half2_rn(v.z, v.w);
        }
        if (tid < 64)
            pnb = use64 ? (int)((const long long*)ei)[NEDGE + tile * 64 + tid]
                        : ((const int*)ei)[NEDGE + tile * 64 + tid];
    }

    for (; tile < NT2; tile += PAIRS) {
        const int e0 = tile * 64;
        __syncthreads();
        #pragma unroll
        for (int q = 0; q < 4; ++q) {
            int i4 = tid + q * 256;
            int er = i4 >> 4, kk = (i4 & 15) * 4;
            __half2* dst = (__half2*)(as_h + er * K2_A_STRIDE + kk);
            dst[0] = pvh[2 * q];
            dst[1] = pvh[2 * q + 1];
        }
        if (tid < 64) nbs[tid] = pnb;
        __syncthreads();

        float acc[2][4][4];
        #pragma unroll
        for (int mt = 0; mt < 2; ++mt)
            #pragma unroll
            for (int nt = 0; nt < 4; ++nt)
                #pragma unroll
                for (int q = 0; q < 4; ++q) acc[mt][nt][q] = 0.0f;

        #pragma unroll
        for (int ks = 0; ks < 4; ++ks) {
            const uint32_t off = ks * 32;
            uint32_t A0[4], A1[4], B0[4], B1[4];
            LDSM_X4(A0, aAddr0 + off);
            LDSM_X4(A1, aAddr1 + off);
            LDSM_X4(B0, bAddr0 + off);
            LDSM_X4(B1, bAddr1 + off);
            mma_f16(acc[0][0], A0, B0);     mma_f16(acc[1][0], A1, B0);
            mma_f16(acc[0][1], A0, B0 + 2); mma_f16(acc[1][1], A1, B0 + 2);
            mma_f16(acc[0][2], A0, B1);     mma_f16(acc[1][2], A1, B1);
            mma_f16(acc[0][3], A0, B1 + 2); mma_f16(acc[1][3], A1, B1 + 2);
        }

        // ---- prefetch next tile (overlaps epilogue gathers) ----
        if (tile + PAIRS < NT2) {
            const float4* src4 = (const float4*)(ea + (size_t)(tile + PAIRS) * 64 * 64);
            #pragma unroll
            for (int q = 0; q < 4; ++q) {
                float4 v = src4[tid + q * 256];
                pvh[2 * q]     = __floats2half2_rn(v.x, v.y);
                pvh[2 * q + 1] = __floats2half2_rn(v.z, v.w);
            }
            if (tid < 64)
                pnb = use64 ? (int)((const long long*)ei)[NEDGE + (tile + PAIRS) * 64 + tid]
                            : ((const int*)ei)[NEDGE + (tile + PAIRS) * 64 + tid];
        }

        // epilogue: + h1[nbr] + h2[src] + bias; store g (fp16, streaming); stats
        #pragma unroll
        for (int mt = 0; mt < 2; ++mt)
            #pragma unroll
            for (int rr = 0; rr < 2; ++rr) {
                const int er = wr + mt * 16 + rr * 8 + g;
                const int e = e0 + er;
                const __half* h1 = g_h + (size_t)nbs[er] * 512 + chb;
                const __half* h2 = g_h + (size_t)(e / 12) * 512 + 256 + chb;
                __half* go = g_g + (size_t)e * 256 + chb;
                #pragma unroll
                for (int nt = 0; nt < 4; ++nt) {
                    int c = wc + nt * 8 + 2 * tg;
                    float2 p1 = __half22float2(*(const __half2*)(h1 + c));
                    float2 p2 = __half22float2(*(const __half2*)(h2 + c));
                    float v0 = acc[mt][nt][rr * 2]     + p1.x + p2.x + bs[c];
                    float v1 = acc[mt][nt][rr * 2 + 1] + p1.y + p2.y + bs[c + 1];
                    stg_cs_h2((__half2*)(go + c), __floats2half2_rn(v0, v1));
                    ssum[nt * 2]     += v0; ssq[nt * 2]     += v0 * v0;
                    ssum[nt * 2 + 1] += v1; ssq[nt * 2 + 1] += v1 * v1;
                }
            }
    }

    // reduce stats across lanes sharing the same columns (xor over g bits)
    #pragma unroll
    for (int q = 0; q < 8; ++q) {
        #pragma unroll
        for (int off = 4; off < 32; off <<= 1) {
            ssum[q] += __shfl_xor_sync(0xFFFFFFFFu, ssum[q], off);
            ssq[q]  += __shfl_xor_sync(0xFFFFFFFFu, ssq[q],  off);
        }
    }
    __syncthreads();
    if (lane < 4) {
        #pragma unroll
        for (int nt = 0; nt < 4; ++nt)
            #pragma unroll
            for (int j = 0; j < 2; ++j) {
                int sl = nt * 8 + 2 * lane + j;
                sred[w * 64 + sl]      = ssum[nt * 2 + j];
                sred[w * 64 + 32 + sl] = ssq[nt * 2 + j];
            }
    }
    __syncthreads();
    if (tid < 128) {
        int c = tid, strip = c >> 5, cl = c & 31;
        float s  = sred[strip * 64 + cl]      + sred[(strip + 4) * 64 + cl];
        float sq = sred[strip * 64 + 32 + cl] + sred[(strip + 4) * 64 + 32 + cl];
        float* dst = g_part1 + (size_t)(pair * 2 + half) * 256;
        dst[c] = s;
        dst[128 + c] = sq;
    }
}

// ---------------- k3: BN1 finalize (warp per channel) ----------------
__global__ void k3_bn1(const float* __restrict__ g1, const float* __restrict__ b1) {
    const int tid = threadIdx.x, lane = tid & 31;
    const int c = blockIdx.x * 8 + (tid >> 5);
    const int half = c >> 7, cl = c & 127;
    float s = 0.0f, q = 0.0f;
    for (int pr = lane; pr < PAIRS; pr += 32) {
        const float* src = g_part1 + (size_t)(pr * 2 + half) * 256;
        s += src[cl];
        q += src[128 + cl];
    }
    #pragma unroll
    for (int off = 16; off > 0; off >>= 1) {
        s += __shfl_xor_sync(0xFFFFFFFFu, s, off);
        q += __shfl_xor_sync(0xFFFFFFFFu, q, off);
    }
    if (lane == 0) {
        float mean = s * (1.0f / (float)NEDGE);
        float var  = q * (1.0f / (float)NEDGE) - mean * mean;
        float rstd = rsqrtf(var + 1e-5f);
        float sc = g1[c] * rstd;
        g_bn1_scale[c] = sc;
        g_bn1_shift[c] = b1[c] - mean * sc;
    }
}

// ---------------- k4: per-node reduce + activations + BN2 partials ----------------
__global__ void __launch_bounds__(256)
k4_reduce() {
    __shared__ float red[8 * 128];
    const int tid = threadIdx.x, lane = tid & 31, wrp = tid >> 5;

    float scf[2][2], shf[2][2], scc[2][2], shc[2][2];
    #pragma unroll
    for (int j = 0; j < 2; ++j)
        #pragma unroll
        for (int q = 0; q < 2; ++q) {
            int c = 2 * lane + 64 * j + q;
            scf[j][q] = g_bn1_scale[c];       shf[j][q] = g_bn1_shift[c];
            scc[j][q] = g_bn1_scale[128 + c]; shc[j][q] = g_bn1_shift[128 + c];
        }
    float stm[2][2] = {{0, 0}, {0, 0}}, stq[2][2] = {{0, 0}, {0, 0}};
    const int base_i = blockIdx.x * 32 + wrp * 4;

    for (int nn = 0; nn < 4; ++nn) {
        int i = base_i + nn;
        if (i < N_NODES) {
            float s[2][2] = {{0, 0}, {0, 0}};
            const __half* grow = g_g + (size_t)i * 12 * 256;
            #pragma unroll
            for (int el = 0; el < 12; ++el) {
                #pragma unroll
                for (int j = 0; j < 2; ++j) {
                    int c = 2 * lane + 64 * j;
                    float2 gf = ldg_cs_h2f((const __half2*)(grow + el * 256 + c));
                    float2 gc = ldg_cs_h2f((const __half2*)(grow + el * 256 + 128 + c));
                    float f0 = gf.x * scf[j][0] + shf[j][0];
                    float f1 = gf.y * scf[j][1] + shf[j][1];
                    float c0 = gc.x * scc[j][0] + shc[j][0];
                    float c1 = gc.y * scc[j][1] + shc[j][1];
                    s[j][0] += sigmoidf_(f0) * softplusf_(c0);
                    s[j][1] += sigmoidf_(f1) * softplusf_(c1);
                }
            }
            #pragma unroll
            for (int j = 0; j < 2; ++j) {
                *(float2*)(g_s + (size_t)i * 128 + 2 * lane + 64 * j) =
                    make_float2(s[j][0], s[j][1]);
                stm[j][0] += s[j][0]; stq[j][0] += s[j][0] * s[j][0];
                stm[j][1] += s[j][1]; stq[j][1] += s[j][1] * s[j][1];
            }
        }
    }

    #pragma unroll
    for (int j = 0; j < 2; ++j)
        #pragma unroll
        for (int q = 0; q < 2; ++q)
            red[wrp * 128 + 2 * lane + 64 * j + q] = stm[j][q];
    __syncthreads();
    if (tid < 128) {
        float t = 0.0f;
        #pragma unroll
        for (int w = 0; w < 8; ++w) t += red[w * 128 + tid];
        g_part2[blockIdx.x * 256 + tid] = t;
    }
    __syncthreads();
    #pragma unroll
    for (int j = 0; j < 2; ++j)
        #pragma unroll
        for (int q = 0; q < 2; ++q)
            red[wrp * 128 + 2 * lane + 64 * j + q] = stq[j][q];
    __syncthreads();
    if (tid < 128) {
        float t = 0.0f;
        #pragma unroll
        for (int w = 0; w < 8; ++w) t += red[w * 128 + tid];
        g_part2[blockIdx.x * 256 + 128 + tid] = t;
    }
}

// ---------------- k5: BN2 finalize ----------------
__global__ void k5_bn2(const float* __restrict__ g2, const float* __restrict__ b2) {
    __shared__ float rs[256], rq[256];
    const int c = blockIdx.x, tid = threadIdx.x;
    float ps = 0.0f, pq = 0.0f;
    for (int bb = tid; bb < GRID4; bb += 256) {
        ps += g_part2[bb * 256 + c];
        pq += g_part2[bb * 256 + 128 + c];
    }
    rs[tid] = ps; rq[tid] = pq;
    __syncthreads();
    for (int off = 128; off > 0; off >>= 1) {
        if (tid < off) { rs[tid] += rs[tid + off]; rq[tid] += rq[tid + off]; }
        __syncthreads();
    }
    if (tid == 0) {
        float mean = rs[0] * (1.0f / (float)N_NODES);
        float var  = rq[0] * (1.0f / (float)N_NODES) - mean * mean;
        float rstd = rsqrtf(var + 1e-5f);
        float sc = g2[c] * rstd;
        g_bn2_scale[c] = sc;
        g_bn2_shift[c] = b2[c] - mean * sc;
    }
}

// ---------------- k6: out = softplus(x + BN2(s)) ----------------
__global__ void k6_final(const float* __restrict__ x, float* __restrict__ out) {
    const int total4 = N_NODES * 32;
    for (int i4 = blockIdx.x * blockDim.x + threadIdx.x; i4 < total4;
         i4 += gridDim.x * blockDim.x) {
        float4 xv = ((const float4*)x)[i4];
        float4 sv = ((const float4*)g_s)[i4];
        int cb = (i4 & 31) << 2;
        float4 o;
        o.x = softplusf_(xv.x + sv.x * g_bn2_scale[cb + 0] + g_bn2_shift[cb + 0]);
        o.y = softplusf_(xv.y + sv.y * g_bn2_scale[cb + 1] + g_bn2_shift[cb + 1]);
        o.z = softplusf_(xv.z + sv.z * g_bn2_scale[cb + 2] + g_bn2_shift[cb + 2]);
        o.w = softplusf_(xv.w + sv.w * g_bn2_scale[cb + 3] + g_bn2_shift[cb + 3]);
        ((float4*)out)[i4] = o;
    }
}

// ---------------- launch ----------------
extern "C" void kernel_launch(void* const* d_in, const int* in_sizes, int n_in,
                              void* d_out, int out_size) {
    const float* x   = (const float*)d_in[0];
    const void*  ei  = d_in[1];
    const float* ea  = (const float*)d_in[2];
    const float* W   = (const float*)d_in[3];
    const float* b   = (const float*)d_in[4];
    const float* b1g = (const float*)d_in[5];
    const float* b1b = (const float*)d_in[6];
    const float* b2g = (const float*)d_in[7];
    const float* b2b = (const float*)d_in[8];
    float* out = (float*)d_out;

    cudaFuncSetAttribute(k1_gemm, cudaFuncAttributeMaxDynamicSharedMemorySize, K1_SMEM);
    cudaFuncSetAttribute(k2_edge, cudaFuncAttributeMaxDynamicSharedMemorySize, K2_SMEM);

    k1_gemm<<<dim3(NT1, 2, 2), 256, K1_SMEM>>>(x, W, ei);
    k2_edge<<<2 * PAIRS, 256, K2_SMEM>>>(ea, ei, W, b);
    k3_bn1<<<32, 256>>>(b1g, b1b);
    k4_reduce<<<GRID4, 256>>>();
    k5_bn2<<<128, 256>>>(b2g, b2b);
    k6_final<<<592, 256>>>(x, out);
}

// round 15
// speedup vs baseline: 1.3876x; 1.3876x over previous
#include <cuda_runtime.h>
#include <cuda_fp16.h>
#include <math.h>
#include <stdint.h>

#define N_NODES 50000
#define NEDGE   600000
#define IN_DIM  320

#define NT1   782          // node tiles of 64 rows
#define NT2   9375         // edge tiles of 64 edges (9375*64 == NEDGE)
#define PAIRS 148          // persistent k2 tile-pair stride (grid = 296)
#define GRID4 1563         // ceil(N_NODES/32)

// ---------------- scratch ----------------
__device__ __half g_h[(size_t)N_NODES * 512];    // 51.2 MB; h2 half carries +bias
__device__ __half g_g[(size_t)NEDGE * 256];      // 307.2 MB
__device__ float  g_s[(size_t)N_NODES * 128];
__device__ float  g_part1[2 * PAIRS * 256];      // [pair*2+half][sum128|sq128]
__device__ float  g_part2[GRID4 * 256];
__device__ float  g_bn1_scale[256], g_bn1_shift[256];
__device__ float  g_bn2_scale[128], g_bn2_shift[128];
__device__ int    g_idx64;

// ---------------- helpers ----------------
__device__ __forceinline__ uint32_t smem_u32(const void* p) {
    uint32_t a;
    asm("{ .reg .u64 t; cvta.to.shared.u64 t, %1; cvt.u32.u64 %0, t; }" : "=r"(a) : "l"(p));
    return a;
}
#define LDSM_X4(r, addr) \
    asm volatile("ldmatrix.sync.aligned.m8n8.x4.shared.b16 {%0,%1,%2,%3}, [%4];" \
        : "=r"((r)[0]), "=r"((r)[1]), "=r"((r)[2]), "=r"((r)[3]) : "r"(addr))

__device__ __forceinline__ void mma_f16(float* d, const uint32_t* a, const uint32_t* b) {
    asm volatile(
        "mma.sync.aligned.m16n8k16.row.col.f32.f16.f16.f32 "
        "{%0,%1,%2,%3}, {%4,%5,%6,%7}, {%8,%9}, {%0,%1,%2,%3};\n"
        : "+f"(d[0]), "+f"(d[1]), "+f"(d[2]), "+f"(d[3])
        : "r"(a[0]), "r"(a[1]), "r"(a[2]), "r"(a[3]), "r"(b[0]), "r"(b[1]));
}
__device__ __forceinline__ float sigmoidf_(float x) {
    return __fdividef(1.0f, 1.0f + __expf(-x));
}
__device__ __forceinline__ float softplusf_(float x) {
    float t = __expf(-fabsf(x));
    return fmaxf(x, 0.0f) + __logf(1.0f + t);
}

// ================= k1: node GEMM (fp16 mma m16n8k16 + LDSM), h fp16 =================
// tile 64 nodes x 128 out, K=128; grid (NT1, 2 input-halves, 2 N-halves)
// y==1 (src/W2 half) folds the linear bias b into h2 before fp16 rounding.
// block (0,0,0) also performs the edge_index dtype detection (k2 runs after k1).
#define K1_W_STRIDE 136                     // halves per W row (128 + 8 pad)
#define K1_A_STRIDE 136
#define K1_W_BYTES (128 * K1_W_STRIDE * 2)  // 34816
#define K1_A_BYTES (64 * K1_A_STRIDE * 2)   // 17408
#define K1_SMEM (K1_W_BYTES + K1_A_BYTES)   // 52224

__global__ void __launch_bounds__(256, 2)
k1_gemm(const float* __restrict__ x, const float* __restrict__ W,
        const float* __restrict__ b, const void* __restrict__ ei) {
    extern __shared__ char smc[];
    __half* wt_h = (__half*)smc;                       // [n 0..127][k 0..127]
    __half* as_h = (__half*)(smc + K1_W_BYTES);        // [row 0..63][k 0..127]

    const int tid = threadIdx.x, lane = tid & 31, w = tid >> 5;
    const int g = lane >> 2, tg = lane & 3;
    const int wr = (w >> 2) * 32, wc = (w & 3) * 32;
    const int i0 = blockIdx.x * 64;
    const int woff = blockIdx.y * 128;
    const int zn = blockIdx.z * 128;

    // fused dtype detect (one block, one thread)
    if (blockIdx.x == 0 && blockIdx.y == 0 && blockIdx.z == 0 && tid == 0) {
        const long long* p = (const long long*)ei;
        int ok = 1;
        #pragma unroll
        for (int q = 0; q < 8; ++q) {
            long long v = p[NEDGE / 2 + q];
            if (v < 0 || v >= N_NODES) ok = 0;
        }
        g_idx64 = ok;
    }

    for (int idx = tid; idx < 128 * 128; idx += 256) {
        int n = idx >> 7, k = idx & 127;
        wt_h[n * K1_W_STRIDE + k] = __float2half_rn(W[(zn + n) * IN_DIM + woff + k]);
    }
    #pragma unroll
    for (int q = 0; q < 8; ++q) {
        int i4 = tid + q * 256;
        int er = i4 >> 5, kk = (i4 & 31) * 4;
        int i = i0 + er;
        float4 v = (i < N_NODES) ? ((const float4*)x)[(size_t)i * 32 + (kk >> 2)]
                                 : make_float4(0.f, 0.f, 0.f, 0.f);
        __half2* dst = (__half2*)(as_h + er * K1_A_STRIDE + kk);
        dst[0] = __floats2half2_rn(v.x, v.y);
        dst[1] = __floats2half2_rn(v.z, v.w);
    }
    __syncthreads();

    const uint32_t sA = smem_u32(as_h), sW = smem_u32(wt_h);
    const uint32_t aAddr0 = sA + (wr + (lane & 15)) * (K1_A_STRIDE * 2) + (lane >> 4) * 16;
    const uint32_t aAddr1 = aAddr0 + 16 * K1_A_STRIDE * 2;
    const uint32_t bAddr0 = sW + (wc + (lane & 7) + ((lane >> 4) & 1) * 8) * (K1_W_STRIDE * 2)
                               + ((lane >> 3) & 1) * 16;
    const uint32_t bAddr1 = bAddr0 + 16 * K1_W_STRIDE * 2;

    float acc[2][4][4];
    #pragma unroll
    for (int mt = 0; mt < 2; ++mt)
        #pragma unroll
        for (int nt = 0; nt < 4; ++nt)
            #pragma unroll
            for (int q = 0; q < 4; ++q) acc[mt][nt][q] = 0.0f;

    #pragma unroll
    for (int ks = 0; ks < 8; ++ks) {
        const uint32_t off = ks * 32;          // 16 halves
        uint32_t A0[4], A1[4], B0[4], B1[4];
        LDSM_X4(A0, aAddr0 + off);
        LDSM_X4(A1, aAddr1 + off);
        LDSM_X4(B0, bAddr0 + off);
        LDSM_X4(B1, bAddr1 + off);
        mma_f16(acc[0][0], A0, B0);     mma_f16(acc[1][0], A1, B0);
        mma_f16(acc[0][1], A0, B0 + 2); mma_f16(acc[1][1], A1, B0 + 2);
        mma_f16(acc[0][2], A0, B1);     mma_f16(acc[1][2], A1, B1);
        mma_f16(acc[0][3], A0, B1 + 2); mma_f16(acc[1][3], A1, B1 + 2);
    }

    // bias fold: h2 half (y==1) carries the linear bias
    float2 bb[4] = {{0, 0}, {0, 0}, {0, 0}, {0, 0}};
    if (blockIdx.y == 1) {
        #pragma unroll
        for (int nt = 0; nt < 4; ++nt)
            bb[nt] = *(const float2*)(b + zn + wc + nt * 8 + 2 * tg);
    }

    const int hoff = blockIdx.y * 256 + zn;
    #pragma unroll
    for (int mt = 0; mt < 2; ++mt)
        #pragma unroll
        for (int rr = 0; rr < 2; ++rr) {
            int i = i0 + wr + mt * 16 + rr * 8 + g;
            if (i < N_NODES) {
                __half* ho = g_h + (size_t)i * 512 + hoff;
                #pragma unroll
                for (int nt = 0; nt < 4; ++nt) {
                    int c = wc + nt * 8 + 2 * tg;
                    *(__half2*)(ho + c) =
                        __floats2half2_rn(acc[mt][nt][rr * 2] + bb[nt].x,
                                          acc[mt][nt][rr * 2 + 1] + bb[nt].y);
                }
            }
        }
}

// ================= k2: edge GEMM half-tile (fp16 mma) + gather + fused BN1 stats =================
#define K2_W_STRIDE 72
#define K2_A_STRIDE 72
#define K2_W_BYTES (128 * K2_W_STRIDE * 2)  // 18432
#define K2_A_BYTES (64 * K2_A_STRIDE * 2)   //  9216
#define K2_NBS_OFF (K2_W_BYTES + K2_A_BYTES)
#define K2_SRED_OFF (K2_NBS_OFF + 64 * 4)
#define K2_SMEM (K2_SRED_OFF + 8 * 64 * 4)  // 29952

__global__ void __launch_bounds__(256, 2)
k2_edge(const float* __restrict__ ea, const void* __restrict__ ei,
        const float* __restrict__ W) {
    extern __shared__ char smc[];
    __half* wt_h = (__half*)smc;                   // [n 0..127][k 0..63]
    __half* as_h = (__half*)(smc + K2_W_BYTES);    // [edge][k]
    int*  nbs = (int*)(smc + K2_NBS_OFF);
    float* sred = (float*)(smc + K2_SRED_OFF);

    const int tid = threadIdx.x, lane = tid & 31, w = tid >> 5;
    const int g = lane >> 2, tg = lane & 3;
    const int wr = (w >> 2) * 32, wc = (w & 3) * 32;
    const int pair = blockIdx.x >> 1, half = blockIdx.x & 1;
    const int chb = half * 128;

    for (int idx = tid; idx < 128 * 64; idx += 256) {
        int n = idx >> 6, k = idx & 63;
        wt_h[n * K2_W_STRIDE + k] = __float2half_rn(W[(chb + n) * IN_DIM + 256 + k]);
    }
    const int use64 = g_idx64;

    const uint32_t sA = smem_u32(as_h), sW = smem_u32(wt_h);
    const uint32_t aAddr0 = sA + (wr + (lane & 15)) * (K2_A_STRIDE * 2) + (lane >> 4) * 16;
    const uint32_t aAddr1 = aAddr0 + 16 * K2_A_STRIDE * 2;
    const uint32_t bAddr0 = sW + (wc + (lane & 7) + ((lane >> 4) & 1) * 8) * (K2_W_STRIDE * 2)
                               + ((lane >> 3) & 1) * 16;
    const uint32_t bAddr1 = bAddr0 + 16 * K2_W_STRIDE * 2;

    float ssum[8], ssq[8];
    #pragma unroll
    for (int q = 0; q < 8; ++q) { ssum[q] = 0.0f; ssq[q] = 0.0f; }

    // ---- prefetch first tile (converted to half2 in regs) ----
    __half2 pvh[8];
    int pnb = 0;
    int tile = pair;
    {
        const float4* src4 = (const float4*)(ea + (size_t)tile * 64 * 64);
        #pragma unroll
        for (int q = 0; q < 4; ++q) {
            float4 v = src4[tid + q * 256];
            pvh[2 * q]     = __floats2half2_rn(v.x, v.y);
            pvh[2 * q + 1] = __floats2half2_rn(v.z, v.w);
        }
        if (tid < 64)
            pnb = use64 ? (int)((const long long*)ei)[NEDGE + tile * 64 + tid]
                        : ((const int*)ei)[NEDGE + tile * 64 + tid];
    }

    for (; tile < NT2; tile += PAIRS) {
        const int e0 = tile * 64;
        __syncthreads();
        #pragma unroll
        for (int q = 0; q < 4; ++q) {
            int i4 = tid + q * 256;
            int er = i4 >> 4, kk = (i4 & 15) * 4;
            __half2* dst = (__half2*)(as_h + er * K2_A_STRIDE + kk);
            dst[0] = pvh[2 * q];
            dst[1] = pvh[2 * q + 1];
        }
        if (tid < 64) nbs[tid] = pnb;
        __syncthreads();

        float acc[2][4][4];
        #pragma unroll
        for (int mt = 0; mt < 2; ++mt)
            #pragma unroll
            for (int nt = 0; nt < 4; ++nt)
                #pragma unroll
                for (int q = 0; q < 4; ++q) acc[mt][nt][q] = 0.0f;

        #pragma unroll
        for (int ks = 0; ks < 4; ++ks) {
            const uint32_t off = ks * 32;
            uint32_t A0[4], A1[4], B0[4], B1[4];
            LDSM_X4(A0, aAddr0 + off);
            LDSM_X4(A1, aAddr1 + off);
            LDSM_X4(B0, bAddr0 + off);
            LDSM_X4(B1, bAddr1 + off);
            mma_f16(acc[0][0], A0, B0);     mma_f16(acc[1][0], A1, B0);
            mma_f16(acc[0][1], A0, B0 + 2); mma_f16(acc[1][1], A1, B0 + 2);
            mma_f16(acc[0][2], A0, B1);     mma_f16(acc[1][2], A1, B1);
            mma_f16(acc[0][3], A0, B1 + 2); mma_f16(acc[1][3], A1, B1 + 2);
        }

        // ---- prefetch next tile (overlaps epilogue gathers) ----
        if (tile + PAIRS < NT2) {
            const float4* src4 = (const float4*)(ea + (size_t)(tile + PAIRS) * 64 * 64);
            #pragma unroll
            for (int q = 0; q < 4; ++q) {
                float4 v = src4[tid + q * 256];
                pvh[2 * q]     = __floats2half2_rn(v.x, v.y);
                pvh[2 * q + 1] = __floats2half2_rn(v.z, v.w);
            }
            if (tid < 64)
                pnb = use64 ? (int)((const long long*)ei)[NEDGE + (tile + PAIRS) * 64 + tid]
                            : ((const int*)ei)[NEDGE + (tile + PAIRS) * 64 + tid];
        }

        // epilogue: + h1[nbr] + h2[src] (bias pre-folded into h2); store g; stats
        #pragma unroll
        for (int mt = 0; mt < 2; ++mt)
            #pragma unroll
            for (int rr = 0; rr < 2; ++rr) {
                const int er = wr + mt * 16 + rr * 8 + g;
                const int e = e0 + er;
                const __half* h1 = g_h + (size_t)nbs[er] * 512 + chb;
                const __half* h2 = g_h + (size_t)(e / 12) * 512 + 256 + chb;
                __half* go = g_g + (size_t)e * 256 + chb;
                #pragma unroll
                for (int nt = 0; nt < 4; ++nt) {
                    int c = wc + nt * 8 + 2 * tg;
                    float2 p1 = __half22float2(*(const __half2*)(h1 + c));
                    float2 p2 = __half22float2(*(const __half2*)(h2 + c));
                    float v0 = acc[mt][nt][rr * 2]     + p1.x + p2.x;
                    float v1 = acc[mt][nt][rr * 2 + 1] + p1.y + p2.y;
                    *(__half2*)(go + c) = __floats2half2_rn(v0, v1);
                    ssum[nt * 2]     += v0; ssq[nt * 2]     += v0 * v0;
                    ssum[nt * 2 + 1] += v1; ssq[nt * 2 + 1] += v1 * v1;
                }
            }
    }

    // reduce stats across lanes sharing the same columns (xor over g bits)
    #pragma unroll
    for (int q = 0; q < 8; ++q) {
        #pragma unroll
        for (int off = 4; off < 32; off <<= 1) {
            ssum[q] += __shfl_xor_sync(0xFFFFFFFFu, ssum[q], off);
            ssq[q]  += __shfl_xor_sync(0xFFFFFFFFu, ssq[q],  off);
        }
    }
    __syncthreads();
    if (lane < 4) {
        #pragma unroll
        for (int nt = 0; nt < 4; ++nt)
            #pragma unroll
            for (int j = 0; j < 2; ++j) {
                int sl = nt * 8 + 2 * lane + j;
                sred[w * 64 + sl]      = ssum[nt * 2 + j];
                sred[w * 64 + 32 + sl] = ssq[nt * 2 + j];
            }
    }
    __syncthreads();
    if (tid < 128) {
        int c = tid, strip = c >> 5, cl = c & 31;
        float s  = sred[strip * 64 + cl]      + sred[(strip + 4) * 64 + cl];
        float sq = sred[strip * 64 + 32 + cl] + sred[(strip + 4) * 64 + 32 + cl];
        float* dst = g_part1 + (size_t)(pair * 2 + half) * 256;
        dst[c] = s;
        dst[128 + c] = sq;
    }
}

// ---------------- k3: BN1 finalize (warp per channel) ----------------
__global__ void k3_bn1(const float* __restrict__ g1, const float* __restrict__ b1) {
    const int tid = threadIdx.x, lane = tid & 31;
    const int c = blockIdx.x * 8 + (tid >> 5);
    const int half = c >> 7, cl = c & 127;
    float s = 0.0f, q = 0.0f;
    for (int pr = lane; pr < PAIRS; pr += 32) {
        const float* src = g_part1 + (size_t)(pr * 2 + half) * 256;
        s += src[cl];
        q += src[128 + cl];
    }
    #pragma unroll
    for (int off = 16; off > 0; off >>= 1) {
        s += __shfl_xor_sync(0xFFFFFFFFu, s, off);
        q += __shfl_xor_sync(0xFFFFFFFFu, q, off);
    }
    if (lane == 0) {
        float mean = s * (1.0f / (float)NEDGE);
        float var  = q * (1.0f / (float)NEDGE) - mean * mean;
        float rstd = rsqrtf(var + 1e-5f);
        float sc = g1[c] * rstd;
        g_bn1_scale[c] = sc;
        g_bn1_shift[c] = b1[c] - mean * sc;
    }
}

// ---------------- k4: per-node reduce + activations + BN2 partials ----------------
__global__ void __launch_bounds__(256)
k4_reduce() {
    __shared__ float red[8 * 128];
    const int tid = threadIdx.x, lane = tid & 31, wrp = tid >> 5;

    float scf[2][2], shf[2][2], scc[2][2], shc[2][2];
    #pragma unroll
    for (int j = 0; j < 2; ++j)
        #pragma unroll
        for (int q = 0; q < 2; ++q) {
            int c = 2 * lane + 64 * j + q;
            scf[j][q] = g_bn1_scale[c];       shf[j][q] = g_bn1_shift[c];
            scc[j][q] = g_bn1_scale[128 + c]; shc[j][q] = g_bn1_shift[128 + c];
        }
    float stm[2][2] = {{0, 0}, {0, 0}}, stq[2][2] = {{0, 0}, {0, 0}};
    const int base_i = blockIdx.x * 32 + wrp * 4;

    for (int nn = 0; nn < 4; ++nn) {
        int i = base_i + nn;
        if (i < N_NODES) {
            float s[2][2] = {{0, 0}, {0, 0}};
            const __half* grow = g_g + (size_t)i * 12 * 256;
            #pragma unroll
            for (int el = 0; el < 12; ++el) {
                #pragma unroll
                for (int j = 0; j < 2; ++j) {
                    int c = 2 * lane + 64 * j;
                    float2 gf = __half22float2(*(const __half2*)(grow + el * 256 + c));
                    float2 gc = __half22float2(*(const __half2*)(grow + el * 256 + 128 + c));
                    float f0 = gf.x * scf[j][0] + shf[j][0];
                    float f1 = gf.y * scf[j][1] + shf[j][1];
                    float c0 = gc.x * scc[j][0] + shc[j][0];
                    float c1 = gc.y * scc[j][1] + shc[j][1];
                    s[j][0] += sigmoidf_(f0) * softplusf_(c0);
                    s[j][1] += sigmoidf_(f1) * softplusf_(c1);
                }
            }
            #pragma unroll
            for (int j = 0; j < 2; ++j) {
                *(float2*)(g_s + (size_t)i * 128 + 2 * lane + 64 * j) =
                    make_float2(s[j][0], s[j][1]);
                stm[j][0] += s[j][0]; stq[j][0] += s[j][0] * s[j][0];
                stm[j][1] += s[j][1]; stq[j][1] += s[j][1] * s[j][1];
            }
        }
    }

    #pragma unroll
    for (int j = 0; j < 2; ++j)
        #pragma unroll
        for (int q = 0; q < 2; ++q)
            red[wrp * 128 + 2 * lane + 64 * j + q] = stm[j][q];
    __syncthreads();
    if (tid < 128) {
        float t = 0.0f;
        #pragma unroll
        for (int w = 0; w < 8; ++w) t += red[w * 128 + tid];
        g_part2[blockIdx.x * 256 + tid] = t;
    }
    __syncthreads();
    #pragma unroll
    for (int j = 0; j < 2; ++j)
        #pragma unroll
        for (int q = 0; q < 2; ++q)
            red[wrp * 128 + 2 * lane + 64 * j + q] = stq[j][q];
    __syncthreads();
    if (tid < 128) {
        float t = 0.0f;
        #pragma unroll
        for (int w = 0; w < 8; ++w) t += red[w * 128 + tid];
        g_part2[blockIdx.x * 256 + 128 + tid] = t;
    }
}

// ---------------- k5: BN2 finalize ----------------
__global__ void k5_bn2(const float* __restrict__ g2, const float* __restrict__ b2) {
    __shared__ float rs[256], rq[256];
    const int c = blockIdx.x, tid = threadIdx.x;
    float ps = 0.0f, pq = 0.0f;
    for (int bb = tid; bb < GRID4; bb += 256) {
        ps += g_part2[bb * 256 + c];
        pq += g_part2[bb * 256 + 128 + c];
    }
    rs[tid] = ps; rq[tid] = pq;
    __syncthreads();
    for (int off = 128; off > 0; off >>= 1) {
        if (tid < off) { rs[tid] += rs[tid + off]; rq[tid] += rq[tid + off]; }
        __syncthreads();
    }
    if (tid == 0) {
        float mean = rs[0] * (1.0f / (float)N_NODES);
        float var  = rq[0] * (1.0f / (float)N_NODES) - mean * mean;
        float rstd = rsqrtf(var + 1e-5f);
        float sc = g2[c] * rstd;
        g_bn2_scale[c] = sc;
        g_bn2_shift[c] = b2[c] - mean * sc;
    }
}

// ---------------- k6: out = softplus(x + BN2(s)) ----------------
__global__ void k6_final(const float* __restrict__ x, float* __restrict__ out) {
    const int total4 = N_NODES * 32;
    for (int i4 = blockIdx.x * blockDim.x + threadIdx.x; i4 < total4;
         i4 += gridDim.x * blockDim.x) {
        float4 xv = ((const float4*)x)[i4];
        float4 sv = ((const float4*)g_s)[i4];
        int cb = (i4 & 31) << 2;
        float4 o;
        o.x = softplusf_(xv.x + sv.x * g_bn2_scale[cb + 0] + g_bn2_shift[cb + 0]);
        o.y = softplusf_(xv.y + sv.y * g_bn2_scale[cb + 1] + g_bn2_shift[cb + 1]);
        o.z = softplusf_(xv.z + sv.z * g_bn2_scale[cb + 2] + g_bn2_shift[cb + 2]);
        o.w = softplusf_(xv.w + sv.w * g_bn2_scale[cb + 3] + g_bn2_shift[cb + 3]);
        ((float4*)out)[i4] = o;
    }
}

// ---------------- launch ----------------
extern "C" void kernel_launch(void* const* d_in, const int* in_sizes, int n_in,
                              void* d_out, int out_size) {
    const float* x   = (const float*)d_in[0];
    const void*  ei  = d_in[1];
    const float* ea  = (const float*)d_in[2];
    const float* W   = (const float*)d_in[3];
    const float* b   = (const float*)d_in[4];
    const float* b1g = (const float*)d_in[5];
    const float* b1b = (const float*)d_in[6];
    const float* b2g = (const float*)d_in[7];
    const float* b2b = (const float*)d_in[8];
    float* out = (float*)d_out;

    cudaFuncSetAttribute(k1_gemm, cudaFuncAttributeMaxDynamicSharedMemorySize, K1_SMEM);
    cudaFuncSetAttribute(k2_edge, cudaFuncAttributeMaxDynamicSharedMemorySize, K2_SMEM);

    k1_gemm<<<dim3(NT1, 2, 2), 256, K1_SMEM>>>(x, W, b, ei);
    k2_edge<<<2 * PAIRS, 256, K2_SMEM>>>(ea, ei, W);
    k3_bn1<<<32, 256>>>(b1g, b1b);
    k4_reduce<<<GRID4, 256>>>();
    k5_bn2<<<128, 256>>>(b2g, b2b);
    k6_final<<<592, 256>>>(x, out);
}